// round 13
// baseline (speedup 1.0000x reference)
#include <cuda_runtime.h>
#include <cuda_fp16.h>

typedef unsigned long long ULL;
typedef unsigned int u32;

// ---------------- f32x2 helpers ----------------
__device__ __forceinline__ ULL pk2(float lo, float hi) {
    ULL r; asm("mov.b64 %0, {%1,%2};" : "=l"(r) : "f"(lo), "f"(hi)); return r;
}
__device__ __forceinline__ void upk2(ULL v, float& lo, float& hi) {
    asm("mov.b64 {%0,%1}, %2;" : "=f"(lo), "=f"(hi) : "l"(v));
}
__device__ __forceinline__ ULL fma2_(ULL a, ULL b, ULL c) {
    ULL d; asm("fma.rn.f32x2 %0, %1, %2, %3;" : "=l"(d) : "l"(a), "l"(b), "l"(c)); return d;
}
__device__ __forceinline__ ULL add2_(ULL a, ULL b) {
    ULL d; asm("add.rn.f32x2 %0, %1, %2;" : "=l"(d) : "l"(a), "l"(b)); return d;
}
__device__ __forceinline__ ULL mul2_(ULL a, ULL b) {
    ULL d; asm("mul.rn.f32x2 %0, %1, %2;" : "=l"(d) : "l"(a), "l"(b)); return d;
}
__device__ __forceinline__ u32 f22h2(float lo, float hi) {
    __half2 h = __floats2half2_rn(lo, hi);
    return *reinterpret_cast<u32*>(&h);
}

// ---------------- packed MUFU-free softplus + sigmoid (known-good) ----------------
__device__ __forceinline__ void act2(float xa, float xb, ULL& sp, ULL& sg)
{
    const ULL MAGIC = pk2(12582912.f, 12582912.f);
    const ULL NEG1  = pk2(-1.f, -1.f);
    const ULL ONE   = pk2(1.f, 1.f);
    const ULL TWO   = pk2(2.f, 2.f);
    const ULL C5 = pk2(1.33335581e-3f, 1.33335581e-3f);
    const ULL C4 = pk2(9.61812910e-3f, 9.61812910e-3f);
    const ULL C3 = pk2(5.55041087e-2f, 5.55041087e-2f);
    const ULL C2 = pk2(2.40226507e-1f, 2.40226507e-1f);
    const ULL C1 = pk2(6.93147182e-1f, 6.93147182e-1f);
    const ULL RI1 = pk2(-0.5f, -0.5f);
    const ULL RK1 = pk2(1.45710678f, 1.45710678f);
    const ULL RI2 = pk2(-0.16666667f, -0.16666667f);
    const ULL RK2 = pk2(0.82491498f, 0.82491498f);
    const ULL A7 = pk2(0.14285714f, 0.14285714f);
    const ULL A5 = pk2(0.2f, 0.2f);
    const ULL A3 = pk2(0.33333333f, 0.33333333f);

    float ya = fmaxf(fabsf(xa) * -1.4426950408889634f, -116.0f);
    float yb = fmaxf(fabsf(xb) * -1.4426950408889634f, -116.0f);
    ULL y  = pk2(ya, yb);
    ULL zz = add2_(y, MAGIC);
    ULL nf = fma2_(MAGIC, NEG1, zz);
    ULL f  = fma2_(nf, NEG1, y);
    float za, zb2; upk2(zz, za, zb2);
    int ia = __float_as_int(za), ibt = __float_as_int(zb2);
    float sa = __int_as_float((int)(((unsigned)(ia  + (127 - 0x4B400000))) << 23));
    float sb = __int_as_float((int)(((unsigned)(ibt + (127 - 0x4B400000))) << 23));
    ULL scale = pk2(sa, sb);
    ULL p = fma2_(C5, f, C4);
    p = fma2_(p, f, C3);
    p = fma2_(p, f, C2);
    p = fma2_(p, f, C1);
    p = fma2_(p, f, ONE);
    ULL u = mul2_(p, scale);
    ULL d1 = add2_(u, ONE);
    ULL r1 = fma2_(d1, RI1, RK1);
    ULL nd1 = mul2_(d1, NEG1);
    ULL m;
    m = fma2_(nd1, r1, TWO); r1 = mul2_(r1, m);
    m = fma2_(nd1, r1, TWO); r1 = mul2_(r1, m);
    ULL d2 = add2_(u, TWO);
    ULL r2 = fma2_(d2, RI2, RK2);
    ULL nd2 = mul2_(d2, NEG1);
    m = fma2_(nd2, r2, TWO); r2 = mul2_(r2, m);
    m = fma2_(nd2, r2, TWO); r2 = mul2_(r2, m);
    ULL s  = mul2_(u, r2);
    ULL s2 = mul2_(s, s);
    ULL q = fma2_(A7, s2, A5);
    q = fma2_(q, s2, A3);
    q = fma2_(q, s2, ONE);
    ULL l1p = mul2_(add2_(s, s), q);
    float mxa = fmaxf(xa, 0.f), mxb = fmaxf(xb, 0.f);
    sp = add2_(pk2(mxa, mxb), l1p);
    float ulo, uhi; upk2(u, ulo, uhi);
    float ga = (xa >= 0.f) ? 1.f : ulo;
    float gb = (xb >= 0.f) ? 1.f : uhi;
    sg = mul2_(r1, pk2(ga, gb));
}

// m16n8k16 fp16 -> f32 MMA (generic-target HMMA)
#define MMA16816(d0,d1,d2,d3,a0,a1,a2,a3,b0,b1) \
    asm volatile("mma.sync.aligned.m16n8k16.row.col.f32.f16.f16.f32 " \
        "{%0,%1,%2,%3}, {%4,%5,%6,%7}, {%8,%9}, {%0,%1,%2,%3};" \
        : "+f"(d0), "+f"(d1), "+f"(d2), "+f"(d3) \
        : "r"(a0), "r"(a1), "r"(a2), "r"(a3), "r"(b0), "r"(b1))

// ---------------- global prep buffer (params + swizzled B image) ----------------
// [0,1024)     w1t/w1z0/w1z1/w1b  ULL[32] each (256B each)
// [1024,2048)  colw float4[64] {w2t, b2, w30, w31}
// [2048,2064)  scal float4 {W3[0][0], W3[1][0], b3[0], b3[1]}
// [2064,+24576) B image: PHI(8192) | PLO(8192) | THI(8192), XOR-swizzled pitch 128
static __device__ __align__(16) unsigned char g_prep[2064 + 24576];

static constexpr int GP_W1T  = 0,    GP_W1Z0 = 256, GP_W1Z1 = 512, GP_W1B = 768;
static constexpr int GP_COLW = 1024, GP_SCAL = 2048, GP_BIMG = 2064;

// smem layout: A_SP [128x128B] | A_SG | B image (24576) = 57344 bytes
static constexpr int A_SP = 0, A_SG = 16384, B_BASE = 32768;
static constexpr int SMEM_BYTES = 57344;

__global__ void ffjord_prep(const float* __restrict__ W1, const float* __restrict__ b1,
                            const float* __restrict__ W2, const float* __restrict__ b2,
                            const float* __restrict__ W3, const float* __restrict__ b3)
{
    int tid = threadIdx.x;
    if (tid < 32) {
        int k = tid;
        ((ULL*)(g_prep + GP_W1T))[k]  = pk2(W1[(2*k)*3+0], W1[(2*k+1)*3+0]);
        ((ULL*)(g_prep + GP_W1Z0))[k] = pk2(W1[(2*k)*3+1], W1[(2*k+1)*3+1]);
        ((ULL*)(g_prep + GP_W1Z1))[k] = pk2(W1[(2*k)*3+2], W1[(2*k+1)*3+2]);
        ((ULL*)(g_prep + GP_W1B))[k]  = pk2(b1[2*k], b1[2*k+1]);
    } else if (tid >= 64) {
        int j = tid - 64;
        ((float4*)(g_prep + GP_COLW))[j] = make_float4(W2[j*65], b2[j], W3[1+j], W3[66+j]);
    }
    if (tid == 0)
        *(float4*)(g_prep + GP_SCAL) = make_float4(W3[0], W3[65], b3[0], b3[1]);

    // B image: 64 rows, 2 threads per row
    int j = tid >> 1;
    int k0 = (tid & 1) * 32;
    float w30 = W3[1 + j], w31 = W3[66 + j];
    for (int k = k0; k < k0 + 32; ++k) {
        float p  = W2[j * 65 + 1 + k];
        float tw = p * fmaf(w30, W1[k * 3 + 1], w31 * W1[k * 3 + 2]);
        __half ph = __float2half_rn(p);
        __half pl = __float2half_rn(p - __half2float(ph));
        __half th = __float2half_rn(tw);
        int off = j * 128 + ((2 * k) ^ ((j & 7) << 4));
        *(__half*)(g_prep + GP_BIMG + off)         = ph;
        *(__half*)(g_prep + GP_BIMG + 8192 + off)  = pl;
        *(__half*)(g_prep + GP_BIMG + 16384 + off) = th;
    }
}

__global__ void __launch_bounds__(128, 4) ffjord_mma_kernel(
    const float2* __restrict__ zin, const float* __restrict__ dlp,
    float* __restrict__ out, int B)
{
    extern __shared__ __align__(16) unsigned char smraw[];
    int tid = threadIdx.x;
    int lane = tid & 31, warp = tid >> 5;
    int g = lane >> 2, t4 = lane & 3;

    // copy prebuilt B image into smem (already swizzled)
    #pragma unroll
    for (int i = 0; i < 12; ++i) {
        int o = (i * 128 + tid) * 16;
        *(uint4*)(smraw + B_BASE + o) = *(const uint4*)(g_prep + GP_BIMG + o);
    }
    __syncthreads();

    const ULL* w1t  = (const ULL*)(g_prep + GP_W1T);
    const ULL* w1z0 = (const ULL*)(g_prep + GP_W1Z0);
    const ULL* w1z1 = (const ULL*)(g_prep + GP_W1Z1);
    const ULL* w1b  = (const ULL*)(g_prep + GP_W1B);
    const float4* colw = (const float4*)(g_prep + GP_COLW);
    float4 scal = *(const float4*)(g_prep + GP_SCAL);

    int gid = blockIdx.x * 128 + tid;
    int gidc = (gid < B) ? gid : (B - 1);
    float2 zv = zin[gidc];
    float z0 = zv.x, z1 = zv.y;
    float lp = dlp[gidc];

    const int rowoff = tid * 128;
    const int xorc = (tid & 7) << 4;
    const int gx = g << 4;

    const float dt = 0.25f;
    #pragma unroll 1
    for (int step = 0; step < 4; ++step) {
        float tbv = (float)step * dt;
        float acc0 = 0.f, acc1 = 0.f, accl = 0.f;
        float pk0v = 0.f, pk1v = 0.f;
        #pragma unroll 1
        for (int s = 0; s < 4; ++s) {
            float cs = (s == 0) ? 0.0f : ((s == 3) ? dt : 0.5f * dt);
            float ws = (s == 1 || s == 2) ? 2.0f : 1.0f;
            float te = tbv + cs;
            float i0 = fmaf(cs, pk0v, z0);
            float i1 = fmaf(cs, pk1v, z1);

            // ---- layer 1: own-row acts -> smem fp16 (XOR-swizzled) ----
            ULL tp = pk2(te, te), z0p = pk2(i0, i0), z1p = pk2(i1, i1);
            #pragma unroll 1
            for (int kq = 0; kq < 8; ++kq) {
                u32 sph[4], sgh[4];
                #pragma unroll
                for (int q = 0; q < 4; ++q) {
                    int kp = kq * 4 + q;
                    ULL x = fma2_(w1t[kp], tp, w1b[kp]);
                    x = fma2_(w1z0[kp], z0p, x);
                    x = fma2_(w1z1[kp], z1p, x);
                    float xa, xb; upk2(x, xa, xb);
                    ULL sp, sg; act2(xa, xb, sp, sg);
                    float spa, spb, sga, sgb;
                    upk2(sp, spa, spb); upk2(sg, sga, sgb);
                    sph[q] = f22h2(spa, spb);
                    sgh[q] = f22h2(sga, sgb);
                }
                int co = rowoff + ((kq * 16) ^ xorc);
                *(uint4*)(smraw + A_SP + co) = make_uint4(sph[0], sph[1], sph[2], sph[3]);
                *(uint4*)(smraw + A_SG + co) = make_uint4(sgh[0], sgh[1], sgh[2], sgh[3]);
            }
            __syncwarp();

            unsigned char* red = smraw + A_SP + warp * 4096;  // own-warp scratch

            // ---- two M-halves of 16 rows each (halves reg pressure) ----
            #pragma unroll 1
            for (int mm = 0; mm < 2; ++mm) {
                // A fragments for this half
                u32 aSP[16], aSG[16];
                #pragma unroll
                for (int k = 0; k < 4; ++k) {
                    int rowa = warp * 32 + mm * 16 + g;
                    int c1 = (k * 32 + t4 * 4) ^ gx;
                    int c2 = (k * 32 + t4 * 4 + 16) ^ gx;
                    int r0 = rowa * 128, r1 = (rowa + 8) * 128;
                    int fi = k * 4;
                    aSP[fi+0] = *(const u32*)(smraw + A_SP + r0 + c1);
                    aSP[fi+1] = *(const u32*)(smraw + A_SP + r1 + c1);
                    aSP[fi+2] = *(const u32*)(smraw + A_SP + r0 + c2);
                    aSP[fi+3] = *(const u32*)(smraw + A_SP + r1 + c2);
                    aSG[fi+0] = *(const u32*)(smraw + A_SG + r0 + c1);
                    aSG[fi+1] = *(const u32*)(smraw + A_SG + r1 + c1);
                    aSG[fi+2] = *(const u32*)(smraw + A_SG + r0 + c2);
                    aSG[fi+3] = *(const u32*)(smraw + A_SG + r1 + c2);
                }

                ULL Zr0 = 0ull, Zr1 = 0ull;
                float tr0 = 0.f, tr1 = 0.f;

                #pragma unroll 1
                for (int n = 0; n < 8; ++n) {
                    float dP[4] = {0.f, 0.f, 0.f, 0.f};
                    float dT[4] = {0.f, 0.f, 0.f, 0.f};
                    #pragma unroll
                    for (int k = 0; k < 4; ++k) {
                        int rb = B_BASE + (n * 8 + g) * 128;
                        int cc1 = (k * 32 + t4 * 4) ^ gx;
                        int cc2 = (k * 32 + t4 * 4 + 16) ^ gx;
                        u32 pbh0 = *(const u32*)(smraw + rb + cc1);
                        u32 pbh1 = *(const u32*)(smraw + rb + cc2);
                        u32 pbl0 = *(const u32*)(smraw + rb + 8192 + cc1);
                        u32 pbl1 = *(const u32*)(smraw + rb + 8192 + cc2);
                        u32 tbh0 = *(const u32*)(smraw + rb + 16384 + cc1);
                        u32 tbh1 = *(const u32*)(smraw + rb + 16384 + cc2);
                        int fi = k * 4;
                        MMA16816(dP[0], dP[1], dP[2], dP[3],
                                 aSP[fi], aSP[fi+1], aSP[fi+2], aSP[fi+3], pbh0, pbh1);
                        MMA16816(dP[0], dP[1], dP[2], dP[3],
                                 aSP[fi], aSP[fi+1], aSP[fi+2], aSP[fi+3], pbl0, pbl1);
                        MMA16816(dT[0], dT[1], dT[2], dT[3],
                                 aSG[fi], aSG[fi+1], aSG[fi+2], aSG[fi+3], tbh0, tbh1);
                    }
                    // epilogue for this n-tile: cols c0 = n*8+2t4, c0+1
                    int c0 = n * 8 + 2 * t4;
                    float4 cw0 = colw[c0];
                    float4 cw1 = colw[c0 + 1];
                    float hb0 = fmaf(cw0.x, te, cw0.y);
                    float hb1 = fmaf(cw1.x, te, cw1.y);
                    ULL w3a = pk2(cw0.z, cw0.w);
                    ULL w3b = pk2(cw1.z, cw1.w);
                    ULL sp2, sg2;
                    float spa, spb, sga, sgb;
                    act2(dP[0] + hb0, dP[1] + hb1, sp2, sg2);
                    upk2(sp2, spa, spb); upk2(sg2, sga, sgb);
                    Zr0 = fma2_(w3a, pk2(spa, spa), Zr0);
                    Zr0 = fma2_(w3b, pk2(spb, spb), Zr0);
                    tr0 = fmaf(sga, dT[0], tr0);
                    tr0 = fmaf(sgb, dT[1], tr0);
                    act2(dP[2] + hb0, dP[3] + hb1, sp2, sg2);
                    upk2(sp2, spa, spb); upk2(sg2, sga, sgb);
                    Zr1 = fma2_(w3a, pk2(spa, spa), Zr1);
                    Zr1 = fma2_(w3b, pk2(spb, spb), Zr1);
                    tr1 = fmaf(sga, dT[2], tr1);
                    tr1 = fmaf(sgb, dT[3], tr1);
                }

                // write per-row partials into own-warp scratch
                // (bytes [0,1536) = A rows 0-11 of this warp, already consumed)
                int row0 = mm * 16 + g;
                float a, b;
                upk2(Zr0, a, b);
                float* pr = (float*)(red + row0 * 48 + t4 * 12);
                pr[0] = a; pr[1] = b; pr[2] = tr0;
                upk2(Zr1, a, b);
                pr = (float*)(red + (row0 + 8) * 48 + t4 * 12);
                pr[0] = a; pr[1] = b; pr[2] = tr1;
            }
            __syncwarp();

            float s0 = 0.f, s1 = 0.f, stv = 0.f;
            #pragma unroll
            for (int q = 0; q < 4; ++q) {
                const float* pr = (const float*)(red + lane * 48 + q * 12);
                s0 += pr[0]; s1 += pr[1]; stv += pr[2];
            }
            __syncwarp();

            float k0 = s0 + fmaf(scal.x, te, scal.z);
            float k1 = s1 + fmaf(scal.y, te, scal.w);
            float klv = -stv;

            acc0 = fmaf(ws, k0, acc0);
            acc1 = fmaf(ws, k1, acc1);
            accl = fmaf(ws, klv, accl);
            pk0v = k0; pk1v = k1;
        }
        const float c6 = dt / 6.0f;
        z0 = fmaf(c6, acc0, z0);
        z1 = fmaf(c6, acc1, z1);
        lp = fmaf(c6, accl, lp);
    }

    if (gid < B) {
        reinterpret_cast<float2*>(out)[gid] = make_float2(z0, z1);  // zf: (B,2)
        out[2 * B + gid] = lp;                                      // delta_logpz: (B,1)
    }
}

extern "C" void kernel_launch(void* const* d_in, const int* in_sizes, int n_in,
                              void* d_out, int out_size) {
    const float2* z  = (const float2*)d_in[0];
    const float* dlp = (const float*)d_in[1];
    const float* W1  = (const float*)d_in[2];
    const float* b1  = (const float*)d_in[3];
    const float* W2  = (const float*)d_in[4];
    const float* b2  = (const float*)d_in[5];
    const float* W3  = (const float*)d_in[6];
    const float* b3  = (const float*)d_in[7];
    float* out = (float*)d_out;
    int B = in_sizes[0] / 2;

    // Host-side, enqueues nothing -> graph-capture safe. Idempotent.
    cudaFuncSetAttribute(ffjord_mma_kernel, cudaFuncAttributeMaxDynamicSharedMemorySize,
                         SMEM_BYTES);

    ffjord_prep<<<1, 128>>>(W1, b1, W2, b2, W3, b3);
    int blocks = (B + 127) / 128;
    ffjord_mma_kernel<<<blocks, 128, SMEM_BYTES>>>(z, dlp, out, B);
}

// round 14
// speedup vs baseline: 1.0023x; 1.0023x over previous
#include <cuda_runtime.h>
#include <cuda_fp16.h>

typedef unsigned long long ULL;
typedef unsigned int u32;

// ---------------- f32x2 helpers ----------------
__device__ __forceinline__ ULL pk2(float lo, float hi) {
    ULL r; asm("mov.b64 %0, {%1,%2};" : "=l"(r) : "f"(lo), "f"(hi)); return r;
}
__device__ __forceinline__ void upk2(ULL v, float& lo, float& hi) {
    asm("mov.b64 {%0,%1}, %2;" : "=f"(lo), "=f"(hi) : "l"(v));
}
__device__ __forceinline__ ULL fma2_(ULL a, ULL b, ULL c) {
    ULL d; asm("fma.rn.f32x2 %0, %1, %2, %3;" : "=l"(d) : "l"(a), "l"(b), "l"(c)); return d;
}
__device__ __forceinline__ ULL add2_(ULL a, ULL b) {
    ULL d; asm("add.rn.f32x2 %0, %1, %2;" : "=l"(d) : "l"(a), "l"(b)); return d;
}
__device__ __forceinline__ ULL mul2_(ULL a, ULL b) {
    ULL d; asm("mul.rn.f32x2 %0, %1, %2;" : "=l"(d) : "l"(a), "l"(b)); return d;
}
__device__ __forceinline__ u32 f22h2(float lo, float hi) {
    __half2 h = __floats2half2_rn(lo, hi);
    return *reinterpret_cast<u32*>(&h);
}
__device__ __forceinline__ float2 h22f2(u32 v) {
    __half2 h = *reinterpret_cast<__half2*>(&v);
    return __half22float2(h);
}

// ---------------- packed MUFU-free softplus + sigmoid (known-good) ----------------
__device__ __forceinline__ void act2(float xa, float xb, ULL& sp, ULL& sg)
{
    const ULL MAGIC = pk2(12582912.f, 12582912.f);
    const ULL NEG1  = pk2(-1.f, -1.f);
    const ULL ONE   = pk2(1.f, 1.f);
    const ULL TWO   = pk2(2.f, 2.f);
    const ULL C5 = pk2(1.33335581e-3f, 1.33335581e-3f);
    const ULL C4 = pk2(9.61812910e-3f, 9.61812910e-3f);
    const ULL C3 = pk2(5.55041087e-2f, 5.55041087e-2f);
    const ULL C2 = pk2(2.40226507e-1f, 2.40226507e-1f);
    const ULL C1 = pk2(6.93147182e-1f, 6.93147182e-1f);
    const ULL RI1 = pk2(-0.5f, -0.5f);
    const ULL RK1 = pk2(1.45710678f, 1.45710678f);
    const ULL RI2 = pk2(-0.16666667f, -0.16666667f);
    const ULL RK2 = pk2(0.82491498f, 0.82491498f);
    const ULL A7 = pk2(0.14285714f, 0.14285714f);
    const ULL A5 = pk2(0.2f, 0.2f);
    const ULL A3 = pk2(0.33333333f, 0.33333333f);

    float ya = fmaxf(fabsf(xa) * -1.4426950408889634f, -116.0f);
    float yb = fmaxf(fabsf(xb) * -1.4426950408889634f, -116.0f);
    ULL y  = pk2(ya, yb);
    ULL zz = add2_(y, MAGIC);
    ULL nf = fma2_(MAGIC, NEG1, zz);
    ULL f  = fma2_(nf, NEG1, y);
    float za, zb2; upk2(zz, za, zb2);
    int ia = __float_as_int(za), ibt = __float_as_int(zb2);
    float sa = __int_as_float((int)(((unsigned)(ia  + (127 - 0x4B400000))) << 23));
    float sb = __int_as_float((int)(((unsigned)(ibt + (127 - 0x4B400000))) << 23));
    ULL scale = pk2(sa, sb);
    ULL p = fma2_(C5, f, C4);
    p = fma2_(p, f, C3);
    p = fma2_(p, f, C2);
    p = fma2_(p, f, C1);
    p = fma2_(p, f, ONE);
    ULL u = mul2_(p, scale);
    ULL d1 = add2_(u, ONE);
    ULL r1 = fma2_(d1, RI1, RK1);
    ULL nd1 = mul2_(d1, NEG1);
    ULL m;
    m = fma2_(nd1, r1, TWO); r1 = mul2_(r1, m);
    m = fma2_(nd1, r1, TWO); r1 = mul2_(r1, m);
    ULL d2 = add2_(u, TWO);
    ULL r2 = fma2_(d2, RI2, RK2);
    ULL nd2 = mul2_(d2, NEG1);
    m = fma2_(nd2, r2, TWO); r2 = mul2_(r2, m);
    m = fma2_(nd2, r2, TWO); r2 = mul2_(r2, m);
    ULL s  = mul2_(u, r2);
    ULL s2 = mul2_(s, s);
    ULL q = fma2_(A7, s2, A5);
    q = fma2_(q, s2, A3);
    q = fma2_(q, s2, ONE);
    ULL l1p = mul2_(add2_(s, s), q);
    float mxa = fmaxf(xa, 0.f), mxb = fmaxf(xb, 0.f);
    sp = add2_(pk2(mxa, mxb), l1p);
    float ulo, uhi; upk2(u, ulo, uhi);
    float ga = (xa >= 0.f) ? 1.f : ulo;
    float gb = (xb >= 0.f) ? 1.f : uhi;
    sg = mul2_(r1, pk2(ga, gb));
}

// m16n8k16 fp16 -> f32 MMA (generic-target HMMA)
#define MMA16816(d0,d1,d2,d3,a0,a1,a2,a3,b0,b1) \
    asm volatile("mma.sync.aligned.m16n8k16.row.col.f32.f16.f16.f32 " \
        "{%0,%1,%2,%3}, {%4,%5,%6,%7}, {%8,%9}, {%0,%1,%2,%3};" \
        : "+f"(d0), "+f"(d1), "+f"(d2), "+f"(d3) \
        : "r"(a0), "r"(a1), "r"(a2), "r"(a3), "r"(b0), "r"(b1))

// ---------------- global prep buffer (params + swizzled B image) ----------------
static __device__ __align__(16) unsigned char g_prep[2064 + 24576];
static constexpr int GP_W1T  = 0,    GP_W1Z0 = 256, GP_W1Z1 = 512, GP_W1B = 768;
static constexpr int GP_COLW = 1024, GP_SCAL = 2048, GP_BIMG = 2064;

// smem: A_SP [128x128B XOR-swizzled] | A_SG | B image (PHI|PLO|THI) = 57344 B
static constexpr int A_SP = 0, A_SG = 16384, B_BASE = 32768;
static constexpr int SMEM_BYTES = 57344;

__global__ void ffjord_prep(const float* __restrict__ W1, const float* __restrict__ b1,
                            const float* __restrict__ W2, const float* __restrict__ b2,
                            const float* __restrict__ W3, const float* __restrict__ b3)
{
    int tid = threadIdx.x;
    if (tid < 32) {
        int k = tid;
        ((ULL*)(g_prep + GP_W1T))[k]  = pk2(W1[(2*k)*3+0], W1[(2*k+1)*3+0]);
        ((ULL*)(g_prep + GP_W1Z0))[k] = pk2(W1[(2*k)*3+1], W1[(2*k+1)*3+1]);
        ((ULL*)(g_prep + GP_W1Z1))[k] = pk2(W1[(2*k)*3+2], W1[(2*k+1)*3+2]);
        ((ULL*)(g_prep + GP_W1B))[k]  = pk2(b1[2*k], b1[2*k+1]);
    } else if (tid >= 64) {
        int j = tid - 64;
        ((float4*)(g_prep + GP_COLW))[j] = make_float4(W2[j*65], b2[j], W3[1+j], W3[66+j]);
    }
    if (tid == 0)
        *(float4*)(g_prep + GP_SCAL) = make_float4(W3[0], W3[65], b3[0], b3[1]);

    int j = tid >> 1;
    int k0 = (tid & 1) * 32;
    float w30 = W3[1 + j], w31 = W3[66 + j];
    for (int k = k0; k < k0 + 32; ++k) {
        float p  = W2[j * 65 + 1 + k];
        float tw = p * fmaf(w30, W1[k * 3 + 1], w31 * W1[k * 3 + 2]);
        __half ph = __float2half_rn(p);
        __half pl = __float2half_rn(p - __half2float(ph));
        __half th = __float2half_rn(tw);
        int off = j * 128 + ((2 * k) ^ ((j & 7) << 4));
        *(__half*)(g_prep + GP_BIMG + off)         = ph;
        *(__half*)(g_prep + GP_BIMG + 8192 + off)  = pl;
        *(__half*)(g_prep + GP_BIMG + 16384 + off) = th;
    }
}

__global__ void __launch_bounds__(128, 4) ffjord_mma_kernel(
    const float2* __restrict__ zin, const float* __restrict__ dlp,
    float* __restrict__ out, int B)
{
    extern __shared__ __align__(16) unsigned char smraw[];
    int tid = threadIdx.x;
    int lane = tid & 31, warp = tid >> 5;
    int g = lane >> 2, t4 = lane & 3;

    // copy prebuilt (already swizzled) B image into smem
    #pragma unroll
    for (int i = 0; i < 12; ++i) {
        int o = (i * 128 + tid) * 16;
        *(uint4*)(smraw + B_BASE + o) = *(const uint4*)(g_prep + GP_BIMG + o);
    }
    __syncthreads();

    const ULL* w1t  = (const ULL*)(g_prep + GP_W1T);
    const ULL* w1z0 = (const ULL*)(g_prep + GP_W1Z0);
    const ULL* w1z1 = (const ULL*)(g_prep + GP_W1Z1);
    const ULL* w1b  = (const ULL*)(g_prep + GP_W1B);
    const float4* colw = (const float4*)(g_prep + GP_COLW);
    float4 scal = *(const float4*)(g_prep + GP_SCAL);

    int gid = blockIdx.x * 128 + tid;
    int gidc = (gid < B) ? gid : (B - 1);
    float2 zv = zin[gidc];
    float z0 = zv.x, z1 = zv.y;
    float lp = dlp[gidc];

    const int rowoff = tid * 128;
    const int xorc = (tid & 7) << 4;
    const int gx = g << 4;
    // hoisted XOR'd fragment column offsets (4 per k-slot pair)
    int c1[4], c2[4];
    #pragma unroll
    for (int k = 0; k < 4; ++k) {
        c1[k] = (k * 32 + t4 * 4) ^ gx;
        c2[k] = (k * 32 + t4 * 4 + 16) ^ gx;
    }

    const float dt = 0.25f;
    #pragma unroll 1
    for (int step = 0; step < 4; ++step) {
        float tbv = (float)step * dt;
        float acc0 = 0.f, acc1 = 0.f, accl = 0.f;
        float pk0v = 0.f, pk1v = 0.f;
        #pragma unroll 1
        for (int s = 0; s < 4; ++s) {
            float cs = (s == 0) ? 0.0f : ((s == 3) ? dt : 0.5f * dt);
            float ws = (s == 1 || s == 2) ? 2.0f : 1.0f;
            float te = tbv + cs;
            float i0 = fmaf(cs, pk0v, z0);
            float i1 = fmaf(cs, pk1v, z1);

            // ---- layer 1: own-row acts -> smem fp16 (XOR-swizzled) ----
            ULL tp = pk2(te, te), z0p = pk2(i0, i0), z1p = pk2(i1, i1);
            #pragma unroll 1
            for (int kq = 0; kq < 8; ++kq) {
                u32 sph[4], sgh[4];
                #pragma unroll
                for (int q = 0; q < 4; ++q) {
                    int kp = kq * 4 + q;
                    ULL x = fma2_(w1t[kp], tp, w1b[kp]);
                    x = fma2_(w1z0[kp], z0p, x);
                    x = fma2_(w1z1[kp], z1p, x);
                    float xa, xb; upk2(x, xa, xb);
                    ULL sp, sg; act2(xa, xb, sp, sg);
                    float spa, spb, sga, sgb;
                    upk2(sp, spa, spb); upk2(sg, sga, sgb);
                    sph[q] = f22h2(spa, spb);
                    sgh[q] = f22h2(sga, sgb);
                }
                int co = rowoff + ((kq * 16) ^ xorc);
                *(uint4*)(smraw + A_SP + co) = make_uint4(sph[0], sph[1], sph[2], sph[3]);
                *(uint4*)(smraw + A_SG + co) = make_uint4(sgh[0], sgh[1], sgh[2], sgh[3]);
            }
            __syncwarp();

            // ================= PASS 1: primal (softplus x W2) =================
            u32 aF[32];
            #pragma unroll
            for (int mm = 0; mm < 2; ++mm) {
                #pragma unroll
                for (int k = 0; k < 4; ++k) {
                    int r0 = (warp * 32 + mm * 16 + g) * 128;
                    int r1 = r0 + 1024;
                    int fi = (mm * 4 + k) * 4;
                    aF[fi+0] = *(const u32*)(smraw + A_SP + r0 + c1[k]);
                    aF[fi+1] = *(const u32*)(smraw + A_SP + r1 + c1[k]);
                    aF[fi+2] = *(const u32*)(smraw + A_SP + r0 + c2[k]);
                    aF[fi+3] = *(const u32*)(smraw + A_SP + r1 + c2[k]);
                }
            }

            ULL Z00 = 0ull, Z01 = 0ull, Z10 = 0ull, Z11 = 0ull; // packed {zd0,zd1}
            u32 sgS[32];                                        // fp16 layer-2 sigmoids

            #pragma unroll 1
            for (int n = 0; n < 8; ++n) {
                float dP0[4] = {0.f,0.f,0.f,0.f};
                float dP1[4] = {0.f,0.f,0.f,0.f};
                int rb = B_BASE + (n * 8 + g) * 128;
                #pragma unroll
                for (int k = 0; k < 4; ++k) {
                    u32 bh0 = *(const u32*)(smraw + rb + c1[k]);
                    u32 bh1 = *(const u32*)(smraw + rb + c2[k]);
                    u32 bl0 = *(const u32*)(smraw + rb + 8192 + c1[k]);
                    u32 bl1 = *(const u32*)(smraw + rb + 8192 + c2[k]);
                    int f0 = k * 4, f1 = 16 + k * 4;
                    MMA16816(dP0[0],dP0[1],dP0[2],dP0[3],
                             aF[f0],aF[f0+1],aF[f0+2],aF[f0+3], bh0,bh1);
                    MMA16816(dP0[0],dP0[1],dP0[2],dP0[3],
                             aF[f0],aF[f0+1],aF[f0+2],aF[f0+3], bl0,bl1);
                    MMA16816(dP1[0],dP1[1],dP1[2],dP1[3],
                             aF[f1],aF[f1+1],aF[f1+2],aF[f1+3], bh0,bh1);
                    MMA16816(dP1[0],dP1[1],dP1[2],dP1[3],
                             aF[f1],aF[f1+1],aF[f1+2],aF[f1+3], bl0,bl1);
                }
                int c0 = n * 8 + 2 * t4;
                float4 cw0 = colw[c0];
                float4 cw1 = colw[c0 + 1];
                float hb0 = fmaf(cw0.x, te, cw0.y);
                float hb1 = fmaf(cw1.x, te, cw1.y);
                ULL w3a = pk2(cw0.z, cw0.w);
                ULL w3b = pk2(cw1.z, cw1.w);
                ULL sp2, sg2; float spa, spb, sga, sgb;
                act2(dP0[0] + hb0, dP0[1] + hb1, sp2, sg2);
                upk2(sp2, spa, spb); upk2(sg2, sga, sgb);
                Z00 = fma2_(w3a, pk2(spa, spa), Z00);
                Z00 = fma2_(w3b, pk2(spb, spb), Z00);
                sgS[n * 4 + 0] = f22h2(sga, sgb);
                act2(dP0[2] + hb0, dP0[3] + hb1, sp2, sg2);
                upk2(sp2, spa, spb); upk2(sg2, sga, sgb);
                Z01 = fma2_(w3a, pk2(spa, spa), Z01);
                Z01 = fma2_(w3b, pk2(spb, spb), Z01);
                sgS[n * 4 + 1] = f22h2(sga, sgb);
                act2(dP1[0] + hb0, dP1[1] + hb1, sp2, sg2);
                upk2(sp2, spa, spb); upk2(sg2, sga, sgb);
                Z10 = fma2_(w3a, pk2(spa, spa), Z10);
                Z10 = fma2_(w3b, pk2(spb, spb), Z10);
                sgS[n * 4 + 2] = f22h2(sga, sgb);
                act2(dP1[2] + hb0, dP1[3] + hb1, sp2, sg2);
                upk2(sp2, spa, spb); upk2(sg2, sga, sgb);
                Z11 = fma2_(w3a, pk2(spa, spa), Z11);
                Z11 = fma2_(w3b, pk2(spb, spb), Z11);
                sgS[n * 4 + 3] = f22h2(sga, sgb);
            }

            // ================= PASS 2: tangent (sigmoid x TW) =================
            #pragma unroll
            for (int mm = 0; mm < 2; ++mm) {
                #pragma unroll
                for (int k = 0; k < 4; ++k) {
                    int r0 = (warp * 32 + mm * 16 + g) * 128;
                    int r1 = r0 + 1024;
                    int fi = (mm * 4 + k) * 4;
                    aF[fi+0] = *(const u32*)(smraw + A_SG + r0 + c1[k]);
                    aF[fi+1] = *(const u32*)(smraw + A_SG + r1 + c1[k]);
                    aF[fi+2] = *(const u32*)(smraw + A_SG + r0 + c2[k]);
                    aF[fi+3] = *(const u32*)(smraw + A_SG + r1 + c2[k]);
                }
            }
            float tr00 = 0.f, tr01 = 0.f, tr10 = 0.f, tr11 = 0.f;

            #pragma unroll 1
            for (int n = 0; n < 8; ++n) {
                float dT0[4] = {0.f,0.f,0.f,0.f};
                float dT1[4] = {0.f,0.f,0.f,0.f};
                int rb = B_BASE + 16384 + (n * 8 + g) * 128;
                #pragma unroll
                for (int k = 0; k < 4; ++k) {
                    u32 th0 = *(const u32*)(smraw + rb + c1[k]);
                    u32 th1 = *(const u32*)(smraw + rb + c2[k]);
                    int f0 = k * 4, f1 = 16 + k * 4;
                    MMA16816(dT0[0],dT0[1],dT0[2],dT0[3],
                             aF[f0],aF[f0+1],aF[f0+2],aF[f0+3], th0,th1);
                    MMA16816(dT1[0],dT1[1],dT1[2],dT1[3],
                             aF[f1],aF[f1+1],aF[f1+2],aF[f1+3], th0,th1);
                }
                float2 s0 = h22f2(sgS[n * 4 + 0]);
                float2 s1 = h22f2(sgS[n * 4 + 1]);
                float2 s2v = h22f2(sgS[n * 4 + 2]);
                float2 s3 = h22f2(sgS[n * 4 + 3]);
                tr00 = fmaf(s0.x, dT0[0], tr00); tr00 = fmaf(s0.y, dT0[1], tr00);
                tr01 = fmaf(s1.x, dT0[2], tr01); tr01 = fmaf(s1.y, dT0[3], tr01);
                tr10 = fmaf(s2v.x, dT1[0], tr10); tr10 = fmaf(s2v.y, dT1[1], tr10);
                tr11 = fmaf(s3.x, dT1[2], tr11); tr11 = fmaf(s3.y, dT1[3], tr11);
            }

            // ---- quad reduction via own-warp smem scratch (A rows consumed) ----
            unsigned char* red = smraw + A_SP + warp * 4096;
            float a, b;
            upk2(Z00, a, b);
            { float* pr = (float*)(red + g * 48 + t4 * 12);          pr[0]=a; pr[1]=b; pr[2]=tr00; }
            upk2(Z01, a, b);
            { float* pr = (float*)(red + (g + 8) * 48 + t4 * 12);    pr[0]=a; pr[1]=b; pr[2]=tr01; }
            upk2(Z10, a, b);
            { float* pr = (float*)(red + (g + 16) * 48 + t4 * 12);   pr[0]=a; pr[1]=b; pr[2]=tr10; }
            upk2(Z11, a, b);
            { float* pr = (float*)(red + (g + 24) * 48 + t4 * 12);   pr[0]=a; pr[1]=b; pr[2]=tr11; }
            __syncwarp();

            float s0 = 0.f, s1 = 0.f, stv = 0.f;
            #pragma unroll
            for (int q = 0; q < 4; ++q) {
                const float* pr = (const float*)(red + lane * 48 + q * 12);
                s0 += pr[0]; s1 += pr[1]; stv += pr[2];
            }
            __syncwarp();

            float k0 = s0 + fmaf(scal.x, te, scal.z);
            float k1 = s1 + fmaf(scal.y, te, scal.w);
            float klv = -stv;

            acc0 = fmaf(ws, k0, acc0);
            acc1 = fmaf(ws, k1, acc1);
            accl = fmaf(ws, klv, accl);
            pk0v = k0; pk1v = k1;
        }
        const float c6 = dt / 6.0f;
        z0 = fmaf(c6, acc0, z0);
        z1 = fmaf(c6, acc1, z1);
        lp = fmaf(c6, accl, lp);
    }

    if (gid < B) {
        reinterpret_cast<float2*>(out)[gid] = make_float2(z0, z1);  // zf: (B,2)
        out[2 * B + gid] = lp;                                      // delta_logpz: (B,1)
    }
}

extern "C" void kernel_launch(void* const* d_in, const int* in_sizes, int n_in,
                              void* d_out, int out_size) {
    const float2* z  = (const float2*)d_in[0];
    const float* dlp = (const float*)d_in[1];
    const float* W1  = (const float*)d_in[2];
    const float* b1  = (const float*)d_in[3];
    const float* W2  = (const float*)d_in[4];
    const float* b2  = (const float*)d_in[5];
    const float* W3  = (const float*)d_in[6];
    const float* b3  = (const float*)d_in[7];
    float* out = (float*)d_out;
    int B = in_sizes[0] / 2;

    // Host-side, enqueues nothing -> graph-capture safe. Idempotent.
    cudaFuncSetAttribute(ffjord_mma_kernel, cudaFuncAttributeMaxDynamicSharedMemorySize,
                         SMEM_BYTES);

    ffjord_prep<<<1, 128>>>(W1, b1, W2, b2, W3, b3);
    int blocks = (B + 127) / 128;
    ffjord_mma_kernel<<<blocks, 128, SMEM_BYTES>>>(z, dlp, out, B);
}

// round 16
// speedup vs baseline: 1.3159x; 1.3128x over previous
#include <cuda_runtime.h>
#include <cuda_fp16.h>

typedef unsigned long long ULL;
typedef unsigned int u32;

// ---------------- f32x2 helpers ----------------
__device__ __forceinline__ ULL pk2(float lo, float hi) {
    ULL r; asm("mov.b64 %0, {%1,%2};" : "=l"(r) : "f"(lo), "f"(hi)); return r;
}
__device__ __forceinline__ void upk2(ULL v, float& lo, float& hi) {
    asm("mov.b64 {%0,%1}, %2;" : "=f"(lo), "=f"(hi) : "l"(v));
}
__device__ __forceinline__ ULL fma2_(ULL a, ULL b, ULL c) {
    ULL d; asm("fma.rn.f32x2 %0, %1, %2, %3;" : "=l"(d) : "l"(a), "l"(b), "l"(c)); return d;
}
__device__ __forceinline__ ULL add2_(ULL a, ULL b) {
    ULL d; asm("add.rn.f32x2 %0, %1, %2;" : "=l"(d) : "l"(a), "l"(b)); return d;
}
__device__ __forceinline__ ULL mul2_(ULL a, ULL b) {
    ULL d; asm("mul.rn.f32x2 %0, %1, %2;" : "=l"(d) : "l"(a), "l"(b)); return d;
}
__device__ __forceinline__ u32 f22h2(float lo, float hi) {
    __half2 h = __floats2half2_rn(lo, hi);
    return *reinterpret_cast<u32*>(&h);
}

// ---------------- packed FMA-pipe softplus + sigmoid (layer-1 burst phase) --------
__device__ __forceinline__ void act2(float xa, float xb, ULL& sp, ULL& sg)
{
    const ULL MAGIC = pk2(12582912.f, 12582912.f);
    const ULL NEG1  = pk2(-1.f, -1.f);
    const ULL ONE   = pk2(1.f, 1.f);
    const ULL TWO   = pk2(2.f, 2.f);
    const ULL C5 = pk2(1.33335581e-3f, 1.33335581e-3f);
    const ULL C4 = pk2(9.61812910e-3f, 9.61812910e-3f);
    const ULL C3 = pk2(5.55041087e-2f, 5.55041087e-2f);
    const ULL C2 = pk2(2.40226507e-1f, 2.40226507e-1f);
    const ULL C1 = pk2(6.93147182e-1f, 6.93147182e-1f);
    const ULL RI1 = pk2(-0.5f, -0.5f);
    const ULL RK1 = pk2(1.45710678f, 1.45710678f);
    const ULL RI2 = pk2(-0.16666667f, -0.16666667f);
    const ULL RK2 = pk2(0.82491498f, 0.82491498f);
    const ULL A7 = pk2(0.14285714f, 0.14285714f);
    const ULL A5 = pk2(0.2f, 0.2f);
    const ULL A3 = pk2(0.33333333f, 0.33333333f);

    float ya = fmaxf(fabsf(xa) * -1.4426950408889634f, -116.0f);
    float yb = fmaxf(fabsf(xb) * -1.4426950408889634f, -116.0f);
    ULL y  = pk2(ya, yb);
    ULL zz = add2_(y, MAGIC);
    ULL nf = fma2_(MAGIC, NEG1, zz);
    ULL f  = fma2_(nf, NEG1, y);
    float za, zb2; upk2(zz, za, zb2);
    int ia = __float_as_int(za), ibt = __float_as_int(zb2);
    float sa = __int_as_float((int)(((unsigned)(ia  + (127 - 0x4B400000))) << 23));
    float sb = __int_as_float((int)(((unsigned)(ibt + (127 - 0x4B400000))) << 23));
    ULL scale = pk2(sa, sb);
    ULL p = fma2_(C5, f, C4);
    p = fma2_(p, f, C3);
    p = fma2_(p, f, C2);
    p = fma2_(p, f, C1);
    p = fma2_(p, f, ONE);
    ULL u = mul2_(p, scale);
    ULL d1 = add2_(u, ONE);
    ULL r1 = fma2_(d1, RI1, RK1);
    ULL nd1 = mul2_(d1, NEG1);
    ULL m;
    m = fma2_(nd1, r1, TWO); r1 = mul2_(r1, m);
    m = fma2_(nd1, r1, TWO); r1 = mul2_(r1, m);
    ULL d2 = add2_(u, TWO);
    ULL r2 = fma2_(d2, RI2, RK2);
    ULL nd2 = mul2_(d2, NEG1);
    m = fma2_(nd2, r2, TWO); r2 = mul2_(r2, m);
    m = fma2_(nd2, r2, TWO); r2 = mul2_(r2, m);
    ULL s  = mul2_(u, r2);
    ULL s2 = mul2_(s, s);
    ULL q = fma2_(A7, s2, A5);
    q = fma2_(q, s2, A3);
    q = fma2_(q, s2, ONE);
    ULL l1p = mul2_(add2_(s, s), q);
    float mxa = fmaxf(xa, 0.f), mxb = fmaxf(xb, 0.f);
    sp = add2_(pk2(mxa, mxb), l1p);
    float ulo, uhi; upk2(u, ulo, uhi);
    float ga = (xa >= 0.f) ? 1.f : ulo;
    float gb = (xb >= 0.f) ? 1.f : uhi;
    sg = mul2_(r1, pk2(ga, gb));
}

// ---------------- MUFU softplus + sigmoid (epilogue, interleaved phase) ----------
// u = exp(-|x|) via MUFU.EX2; softplus = max(x,0)+lg2(1+u)*ln2; sigmoid via MUFU.RCP.
__device__ __forceinline__ void act1m(float x, float& sp, float& sg) {
    float u;
    asm("ex2.approx.f32 %0, %1;" : "=f"(u) : "f"(fabsf(x) * -1.4426950408889634f));
    float opu = 1.0f + u;
    float lg, r;
    asm("lg2.approx.f32 %0, %1;" : "=f"(lg) : "f"(opu));
    asm("rcp.approx.f32 %0, %1;" : "=f"(r)  : "f"(opu));
    sp = fmaxf(x, 0.0f) + lg * 0.69314718055994531f;
    sg = r * ((x >= 0.0f) ? 1.0f : u);
}

// m16n8k16 fp16 -> f32 MMA (generic-target HMMA)
#define MMA16816(d0,d1,d2,d3,a0,a1,a2,a3,b0,b1) \
    asm volatile("mma.sync.aligned.m16n8k16.row.col.f32.f16.f16.f32 " \
        "{%0,%1,%2,%3}, {%4,%5,%6,%7}, {%8,%9}, {%0,%1,%2,%3};" \
        : "+f"(d0), "+f"(d1), "+f"(d2), "+f"(d3) \
        : "r"(a0), "r"(a1), "r"(a2), "r"(a3), "r"(b0), "r"(b1))

// ---------------- smem layout (pitch 144B keeps all LDS conflict-free) ----
static constexpr int PITCH   = 144;              // 64 fp16 = 128B + 16B pad
static constexpr int A_SPHI  = 0;                // softplus acts fp16 [128 rows]
static constexpr int A_SGHI  = 18432;            // sigmoid  acts fp16
static constexpr int B_PHI   = 36864;            // W2 primal hi [64 n][64 k]
static constexpr int B_PLO   = 46080;            // W2 primal lo
static constexpr int B_THI   = 55296;            // folded tangent (hi only)
static constexpr int W1T_O   = 64512, W1Z0_O = 64768, W1Z1_O = 65024, W1B_O = 65280;
static constexpr int COLW_O  = 65536;            // float4[64] {w2t, b2, w30, w31}
static constexpr int SCAL_O  = 66560;            // float4 {W3[0][0], W3[1][0], b3[0], b3[1]}
static constexpr int SMEM_BYTES = 66576;

__global__ void __launch_bounds__(128, 3) ffjord_mma_kernel(
    const float2* __restrict__ zin, const float* __restrict__ dlp,
    const float* __restrict__ W1, const float* __restrict__ b1,
    const float* __restrict__ W2, const float* __restrict__ b2,
    const float* __restrict__ W3, const float* __restrict__ b3,
    float* __restrict__ out, int B)
{
    extern __shared__ __align__(16) unsigned char smraw[];
    int tid = threadIdx.x;
    int lane = tid & 31, warp = tid >> 5;
    int g = lane >> 2, t4 = lane & 3;

    // ---- stage B weight tiles ----
    if (tid < 64) {
        int j = tid;
        float w30 = W3[1 + j], w31 = W3[66 + j];
        for (int k = 0; k < 64; ++k) {
            float p  = W2[j * 65 + 1 + k];
            float tw = p * fmaf(w30, W1[k * 3 + 1], w31 * W1[k * 3 + 2]);
            __half ph = __float2half_rn(p);
            __half pl = __float2half_rn(p - __half2float(ph));
            __half th = __float2half_rn(tw);
            int off = j * PITCH + k * 2;
            *(__half*)(smraw + B_PHI + off) = ph;
            *(__half*)(smraw + B_PLO + off) = pl;
            *(__half*)(smraw + B_THI + off) = th;
        }
    }
    if (tid < 32) {
        int k = tid;   // unit pair (2k, 2k+1)
        ((ULL*)(smraw + W1T_O))[k]  = pk2(W1[(2 * k) * 3 + 0], W1[(2 * k + 1) * 3 + 0]);
        ((ULL*)(smraw + W1Z0_O))[k] = pk2(W1[(2 * k) * 3 + 1], W1[(2 * k + 1) * 3 + 1]);
        ((ULL*)(smraw + W1Z1_O))[k] = pk2(W1[(2 * k) * 3 + 2], W1[(2 * k + 1) * 3 + 2]);
        ((ULL*)(smraw + W1B_O))[k]  = pk2(b1[2 * k], b1[2 * k + 1]);
    } else if (tid >= 64) {
        int j = tid - 64;
        ((float4*)(smraw + COLW_O))[j] =
            make_float4(W2[j * 65 + 0], b2[j], W3[1 + j], W3[66 + j]);
    }
    if (tid == 0)
        *(float4*)(smraw + SCAL_O) = make_float4(W3[0], W3[65], b3[0], b3[1]);
    __syncthreads();

    const ULL* w1t  = (const ULL*)(smraw + W1T_O);
    const ULL* w1z0 = (const ULL*)(smraw + W1Z0_O);
    const ULL* w1z1 = (const ULL*)(smraw + W1Z1_O);
    const ULL* w1b  = (const ULL*)(smraw + W1B_O);
    const float4* colw = (const float4*)(smraw + COLW_O);
    float4 scal = *(const float4*)(smraw + SCAL_O);

    int gid = blockIdx.x * 128 + tid;
    int gidc = (gid < B) ? gid : (B - 1);
    float2 zv = zin[gidc];
    float z0 = zv.x, z1 = zv.y;
    float lp = dlp[gidc];

    const int rowoff = tid * PITCH;

    const float dt = 0.25f;
    #pragma unroll 1
    for (int step = 0; step < 4; ++step) {
        float tbv = (float)step * dt;
        float acc0 = 0.f, acc1 = 0.f, accl = 0.f;
        float pk0v = 0.f, pk1v = 0.f;
        #pragma unroll 1
        for (int s = 0; s < 4; ++s) {
            float cs = (s == 0) ? 0.0f : ((s == 3) ? dt : 0.5f * dt);
            float ws = (s == 1 || s == 2) ? 2.0f : 1.0f;
            float te = tbv + cs;
            float i0 = fmaf(cs, pk0v, z0);
            float i1 = fmaf(cs, pk1v, z1);

            // ---- layer 1: own-row acts -> smem fp16 (packed FMA act) ----
            ULL tp = pk2(te, te), z0p = pk2(i0, i0), z1p = pk2(i1, i1);
            #pragma unroll 1
            for (int kq = 0; kq < 8; ++kq) {
                u32 sph[4], sgh[4];
                #pragma unroll
                for (int q = 0; q < 4; ++q) {
                    int kp = kq * 4 + q;
                    ULL x = fma2_(w1t[kp], tp, w1b[kp]);
                    x = fma2_(w1z0[kp], z0p, x);
                    x = fma2_(w1z1[kp], z1p, x);
                    float xa, xb; upk2(x, xa, xb);
                    ULL sp, sg; act2(xa, xb, sp, sg);
                    float spa, spb, sga, sgb;
                    upk2(sp, spa, spb); upk2(sg, sga, sgb);
                    sph[q] = f22h2(spa, spb);
                    sgh[q] = f22h2(sga, sgb);
                }
                int co = rowoff + kq * 16;
                *(uint4*)(smraw + A_SPHI + co) = make_uint4(sph[0], sph[1], sph[2], sph[3]);
                *(uint4*)(smraw + A_SGHI + co) = make_uint4(sgh[0], sgh[1], sgh[2], sgh[3]);
            }
            __syncwarp();

            // ---- load A fragments (persistent in registers) ----
            u32 aSPH[32], aSGH[32];
            #pragma unroll
            for (int mm = 0; mm < 2; ++mm) {
                #pragma unroll
                for (int k = 0; k < 4; ++k) {
                    int r0b = (warp * 32 + mm * 16 + g) * PITCH + k * 32 + t4 * 4;
                    int r1b = r0b + 8 * PITCH;
                    int fi = (mm * 4 + k) * 4;
                    aSPH[fi+0] = *(const u32*)(smraw + A_SPHI + r0b);
                    aSPH[fi+1] = *(const u32*)(smraw + A_SPHI + r1b);
                    aSPH[fi+2] = *(const u32*)(smraw + A_SPHI + r0b + 16);
                    aSPH[fi+3] = *(const u32*)(smraw + A_SPHI + r1b + 16);
                    aSGH[fi+0] = *(const u32*)(smraw + A_SGHI + r0b);
                    aSGH[fi+1] = *(const u32*)(smraw + A_SGHI + r1b);
                    aSGH[fi+2] = *(const u32*)(smraw + A_SGHI + r0b + 16);
                    aSGH[fi+3] = *(const u32*)(smraw + A_SGHI + r1b + 16);
                }
            }

            float zr0[4] = {0.f, 0.f, 0.f, 0.f};
            float zr1[4] = {0.f, 0.f, 0.f, 0.f};
            float trr[4] = {0.f, 0.f, 0.f, 0.f};

            #pragma unroll 1
            for (int n = 0; n < 8; ++n) {
                float dP[2][4] = {{0.f,0.f,0.f,0.f},{0.f,0.f,0.f,0.f}};
                float dT[2][4] = {{0.f,0.f,0.f,0.f},{0.f,0.f,0.f,0.f}};
                #pragma unroll
                for (int k = 0; k < 4; ++k) {
                    int bb = (n * 8 + g) * PITCH + k * 32 + t4 * 4;
                    u32 pbh0 = *(const u32*)(smraw + B_PHI + bb);
                    u32 pbh1 = *(const u32*)(smraw + B_PHI + bb + 16);
                    u32 pbl0 = *(const u32*)(smraw + B_PLO + bb);
                    u32 pbl1 = *(const u32*)(smraw + B_PLO + bb + 16);
                    u32 tbh0 = *(const u32*)(smraw + B_THI + bb);
                    u32 tbh1 = *(const u32*)(smraw + B_THI + bb + 16);
                    #pragma unroll
                    for (int mm = 0; mm < 2; ++mm) {
                        int fi = (mm * 4 + k) * 4;
                        MMA16816(dP[mm][0],dP[mm][1],dP[mm][2],dP[mm][3],
                                 aSPH[fi],aSPH[fi+1],aSPH[fi+2],aSPH[fi+3], pbh0,pbh1);
                        MMA16816(dP[mm][0],dP[mm][1],dP[mm][2],dP[mm][3],
                                 aSPH[fi],aSPH[fi+1],aSPH[fi+2],aSPH[fi+3], pbl0,pbl1);
                        MMA16816(dT[mm][0],dT[mm][1],dT[mm][2],dT[mm][3],
                                 aSGH[fi],aSGH[fi+1],aSGH[fi+2],aSGH[fi+3], tbh0,tbh1);
                    }
                }
                // epilogue for this n-tile: cols c0 = n*8+2t4, c0+1 (MUFU acts,
                // interleaved with surrounding MMA/FMA -> no MUFU burst)
                int c0 = n * 8 + 2 * t4;
                float4 cw0 = colw[c0];
                float4 cw1 = colw[c0 + 1];
                float hb0 = fmaf(cw0.x, te, cw0.y);
                float hb1 = fmaf(cw1.x, te, cw1.y);
                #pragma unroll
                for (int mm = 0; mm < 2; ++mm) {
                    float spa, spb, sga, sgb;
                    act1m(dP[mm][0] + hb0, spa, sga);
                    act1m(dP[mm][1] + hb1, spb, sgb);
                    zr0[2*mm] = fmaf(cw0.z, spa, zr0[2*mm]);
                    zr0[2*mm] = fmaf(cw1.z, spb, zr0[2*mm]);
                    zr1[2*mm] = fmaf(cw0.w, spa, zr1[2*mm]);
                    zr1[2*mm] = fmaf(cw1.w, spb, zr1[2*mm]);
                    trr[2*mm] = fmaf(sga, dT[mm][0], trr[2*mm]);
                    trr[2*mm] = fmaf(sgb, dT[mm][1], trr[2*mm]);
                    act1m(dP[mm][2] + hb0, spa, sga);
                    act1m(dP[mm][3] + hb1, spb, sgb);
                    zr0[2*mm+1] = fmaf(cw0.z, spa, zr0[2*mm+1]);
                    zr0[2*mm+1] = fmaf(cw1.z, spb, zr0[2*mm+1]);
                    zr1[2*mm+1] = fmaf(cw0.w, spa, zr1[2*mm+1]);
                    zr1[2*mm+1] = fmaf(cw1.w, spb, zr1[2*mm+1]);
                    trr[2*mm+1] = fmaf(sga, dT[mm][2], trr[2*mm+1]);
                    trr[2*mm+1] = fmaf(sgb, dT[mm][3], trr[2*mm+1]);
                }
            }

            // ---- quad reduction via per-warp smem scratch (aliases consumed A rows)
            unsigned char* red = smraw + A_SPHI + warp * 32 * PITCH;
            #pragma unroll
            for (int r4 = 0; r4 < 4; ++r4) {
                int row = r4 * 8 + g;
                float* pr = (float*)(red + row * 48 + t4 * 12);
                pr[0] = zr0[r4]; pr[1] = zr1[r4]; pr[2] = trr[r4];
            }
            __syncwarp();
            float s0 = 0.f, s1 = 0.f, stv = 0.f;
            #pragma unroll
            for (int q = 0; q < 4; ++q) {
                const float* pr = (const float*)(red + lane * 48 + q * 12);
                s0 += pr[0]; s1 += pr[1]; stv += pr[2];
            }
            __syncwarp();

            float k0 = s0 + fmaf(scal.x, te, scal.z);
            float k1 = s1 + fmaf(scal.y, te, scal.w);
            float klv = -stv;

            acc0 = fmaf(ws, k0, acc0);
            acc1 = fmaf(ws, k1, acc1);
            accl = fmaf(ws, klv, accl);
            pk0v = k0; pk1v = k1;
        }
        const float c6 = dt / 6.0f;
        z0 = fmaf(c6, acc0, z0);
        z1 = fmaf(c6, acc1, z1);
        lp = fmaf(c6, accl, lp);
    }

    if (gid < B) {
        reinterpret_cast<float2*>(out)[gid] = make_float2(z0, z1);  // zf: (B,2)
        out[2 * B + gid] = lp;                                      // delta_logpz: (B,1)
    }
}

extern "C" void kernel_launch(void* const* d_in, const int* in_sizes, int n_in,
                              void* d_out, int out_size) {
    const float2* z  = (const float2*)d_in[0];
    const float* dlp = (const float*)d_in[1];
    const float* W1  = (const float*)d_in[2];
    const float* b1  = (const float*)d_in[3];
    const float* W2  = (const float*)d_in[4];
    const float* b2  = (const float*)d_in[5];
    const float* W3  = (const float*)d_in[6];
    const float* b3  = (const float*)d_in[7];
    float* out = (float*)d_out;
    int B = in_sizes[0] / 2;

    // Host-side, enqueues nothing -> graph-capture safe. Idempotent.
    cudaFuncSetAttribute(ffjord_mma_kernel, cudaFuncAttributeMaxDynamicSharedMemorySize,
                         SMEM_BYTES);

    int blocks = (B + 127) / 128;
    ffjord_mma_kernel<<<blocks, 128, SMEM_BYTES>>>(z, dlp, W1, b1, W2, b2, W3, b3, out, B);
}

// round 17
// speedup vs baseline: 1.5819x; 1.2022x over previous
#include <cuda_runtime.h>
#include <cuda_fp16.h>

typedef unsigned long long ULL;
typedef unsigned int u32;

// ---------------- f32x2 helpers ----------------
__device__ __forceinline__ ULL pk2(float lo, float hi) {
    ULL r; asm("mov.b64 %0, {%1,%2};" : "=l"(r) : "f"(lo), "f"(hi)); return r;
}
__device__ __forceinline__ void upk2(ULL v, float& lo, float& hi) {
    asm("mov.b64 {%0,%1}, %2;" : "=f"(lo), "=f"(hi) : "l"(v));
}
__device__ __forceinline__ ULL fma2_(ULL a, ULL b, ULL c) {
    ULL d; asm("fma.rn.f32x2 %0, %1, %2, %3;" : "=l"(d) : "l"(a), "l"(b), "l"(c)); return d;
}
__device__ __forceinline__ u32 f22h2(float lo, float hi) {
    __half2 h = __floats2half2_rn(lo, hi);
    return *reinterpret_cast<u32*>(&h);
}

// ---------------- MUFU softplus + sigmoid ----------------
// u = exp(-|x|) via MUFU.EX2; softplus = max(x,0)+lg2(1+u)*ln2; sigmoid via MUFU.RCP.
// err ~2^-21; independent chains interleave with surrounding FMA/MMA issue.
__device__ __forceinline__ void act1m(float x, float& sp, float& sg) {
    float u;
    asm("ex2.approx.f32 %0, %1;" : "=f"(u) : "f"(fabsf(x) * -1.4426950408889634f));
    float opu = 1.0f + u;
    float lg, r;
    asm("lg2.approx.f32 %0, %1;" : "=f"(lg) : "f"(opu));
    asm("rcp.approx.f32 %0, %1;" : "=f"(r)  : "f"(opu));
    sp = fmaxf(x, 0.0f) + lg * 0.69314718055994531f;
    sg = r * ((x >= 0.0f) ? 1.0f : u);
}

// m16n8k16 fp16 -> f32 MMA (generic-target HMMA)
#define MMA16816(d0,d1,d2,d3,a0,a1,a2,a3,b0,b1) \
    asm volatile("mma.sync.aligned.m16n8k16.row.col.f32.f16.f16.f32 " \
        "{%0,%1,%2,%3}, {%4,%5,%6,%7}, {%8,%9}, {%0,%1,%2,%3};" \
        : "+f"(d0), "+f"(d1), "+f"(d2), "+f"(d3) \
        : "r"(a0), "r"(a1), "r"(a2), "r"(a3), "r"(b0), "r"(b1))

// ---------------- smem layout (pitch 144B keeps all LDS conflict-free) ----
static constexpr int PITCH   = 144;              // 64 fp16 = 128B + 16B pad
static constexpr int A_SPHI  = 0;                // softplus acts fp16 [128 rows]
static constexpr int A_SGHI  = 18432;            // sigmoid  acts fp16
static constexpr int B_PHI   = 36864;            // W2 primal hi [64 n][64 k]
static constexpr int B_PLO   = 46080;            // W2 primal lo
static constexpr int B_THI   = 55296;            // folded tangent (hi only)
static constexpr int W1T_O   = 64512, W1Z0_O = 64768, W1Z1_O = 65024, W1B_O = 65280;
static constexpr int COLW_O  = 65536;            // float4[64] {w2t, b2, w30, w31}
static constexpr int SCAL_O  = 66560;            // float4 {W3[0][0], W3[1][0], b3[0], b3[1]}
static constexpr int SMEM_BYTES = 66576;

__global__ void __launch_bounds__(128, 3) ffjord_mma_kernel(
    const float2* __restrict__ zin, const float* __restrict__ dlp,
    const float* __restrict__ W1, const float* __restrict__ b1,
    const float* __restrict__ W2, const float* __restrict__ b2,
    const float* __restrict__ W3, const float* __restrict__ b3,
    float* __restrict__ out, int B)
{
    extern __shared__ __align__(16) unsigned char smraw[];
    int tid = threadIdx.x;
    int lane = tid & 31, warp = tid >> 5;
    int g = lane >> 2, t4 = lane & 3;

    // ---- stage B weight tiles ----
    if (tid < 64) {
        int j = tid;
        float w30 = W3[1 + j], w31 = W3[66 + j];
        for (int k = 0; k < 64; ++k) {
            float p  = W2[j * 65 + 1 + k];
            float tw = p * fmaf(w30, W1[k * 3 + 1], w31 * W1[k * 3 + 2]);
            __half ph = __float2half_rn(p);
            __half pl = __float2half_rn(p - __half2float(ph));
            __half th = __float2half_rn(tw);
            int off = j * PITCH + k * 2;
            *(__half*)(smraw + B_PHI + off) = ph;
            *(__half*)(smraw + B_PLO + off) = pl;
            *(__half*)(smraw + B_THI + off) = th;
        }
    }
    if (tid < 32) {
        int k = tid;   // unit pair (2k, 2k+1)
        ((ULL*)(smraw + W1T_O))[k]  = pk2(W1[(2 * k) * 3 + 0], W1[(2 * k + 1) * 3 + 0]);
        ((ULL*)(smraw + W1Z0_O))[k] = pk2(W1[(2 * k) * 3 + 1], W1[(2 * k + 1) * 3 + 1]);
        ((ULL*)(smraw + W1Z1_O))[k] = pk2(W1[(2 * k) * 3 + 2], W1[(2 * k + 1) * 3 + 2]);
        ((ULL*)(smraw + W1B_O))[k]  = pk2(b1[2 * k], b1[2 * k + 1]);
    } else if (tid >= 64) {
        int j = tid - 64;
        ((float4*)(smraw + COLW_O))[j] =
            make_float4(W2[j * 65 + 0], b2[j], W3[1 + j], W3[66 + j]);
    }
    if (tid == 0)
        *(float4*)(smraw + SCAL_O) = make_float4(W3[0], W3[65], b3[0], b3[1]);
    __syncthreads();

    const ULL* w1t  = (const ULL*)(smraw + W1T_O);
    const ULL* w1z0 = (const ULL*)(smraw + W1Z0_O);
    const ULL* w1z1 = (const ULL*)(smraw + W1Z1_O);
    const ULL* w1b  = (const ULL*)(smraw + W1B_O);
    const float4* colw = (const float4*)(smraw + COLW_O);
    float4 scal = *(const float4*)(smraw + SCAL_O);

    int gid = blockIdx.x * 128 + tid;
    int gidc = (gid < B) ? gid : (B - 1);
    float2 zv = zin[gidc];
    float z0 = zv.x, z1 = zv.y;
    float lp = dlp[gidc];

    const int rowoff = tid * PITCH;

    const float dt = 0.25f;
    #pragma unroll 1
    for (int step = 0; step < 4; ++step) {
        float tbv = (float)step * dt;
        float acc0 = 0.f, acc1 = 0.f, accl = 0.f;
        float pk0v = 0.f, pk1v = 0.f;
        #pragma unroll 1
        for (int s = 0; s < 4; ++s) {
            float cs = (s == 0) ? 0.0f : ((s == 3) ? dt : 0.5f * dt);
            float ws = (s == 1 || s == 2) ? 2.0f : 1.0f;
            float te = tbv + cs;
            float i0 = fmaf(cs, pk0v, z0);
            float i1 = fmaf(cs, pk1v, z1);

            // ---- layer 1: own-row acts -> smem fp16 (MUFU acts, 8 indep chains/iter)
            ULL tp = pk2(te, te), z0p = pk2(i0, i0), z1p = pk2(i1, i1);
            #pragma unroll 1
            for (int kq = 0; kq < 8; ++kq) {
                u32 sph[4], sgh[4];
                #pragma unroll
                for (int q = 0; q < 4; ++q) {
                    int kp = kq * 4 + q;
                    ULL x = fma2_(w1t[kp], tp, w1b[kp]);
                    x = fma2_(w1z0[kp], z0p, x);
                    x = fma2_(w1z1[kp], z1p, x);
                    float xa, xb; upk2(x, xa, xb);
                    float spa, sga, spb, sgb;
                    act1m(xa, spa, sga);
                    act1m(xb, spb, sgb);
                    sph[q] = f22h2(spa, spb);
                    sgh[q] = f22h2(sga, sgb);
                }
                int co = rowoff + kq * 16;
                *(uint4*)(smraw + A_SPHI + co) = make_uint4(sph[0], sph[1], sph[2], sph[3]);
                *(uint4*)(smraw + A_SGHI + co) = make_uint4(sgh[0], sgh[1], sgh[2], sgh[3]);
            }
            __syncwarp();

            // ---- load A fragments (persistent in registers) ----
            u32 aSPH[32], aSGH[32];
            #pragma unroll
            for (int mm = 0; mm < 2; ++mm) {
                #pragma unroll
                for (int k = 0; k < 4; ++k) {
                    int r0b = (warp * 32 + mm * 16 + g) * PITCH + k * 32 + t4 * 4;
                    int r1b = r0b + 8 * PITCH;
                    int fi = (mm * 4 + k) * 4;
                    aSPH[fi+0] = *(const u32*)(smraw + A_SPHI + r0b);
                    aSPH[fi+1] = *(const u32*)(smraw + A_SPHI + r1b);
                    aSPH[fi+2] = *(const u32*)(smraw + A_SPHI + r0b + 16);
                    aSPH[fi+3] = *(const u32*)(smraw + A_SPHI + r1b + 16);
                    aSGH[fi+0] = *(const u32*)(smraw + A_SGHI + r0b);
                    aSGH[fi+1] = *(const u32*)(smraw + A_SGHI + r1b);
                    aSGH[fi+2] = *(const u32*)(smraw + A_SGHI + r0b + 16);
                    aSGH[fi+3] = *(const u32*)(smraw + A_SGHI + r1b + 16);
                }
            }

            float zr0[4] = {0.f, 0.f, 0.f, 0.f};
            float zr1[4] = {0.f, 0.f, 0.f, 0.f};
            float trr[4] = {0.f, 0.f, 0.f, 0.f};

            #pragma unroll 1
            for (int n = 0; n < 8; ++n) {
                float dP[2][4] = {{0.f,0.f,0.f,0.f},{0.f,0.f,0.f,0.f}};
                float dT[2][4] = {{0.f,0.f,0.f,0.f},{0.f,0.f,0.f,0.f}};
                #pragma unroll
                for (int k = 0; k < 4; ++k) {
                    int bb = (n * 8 + g) * PITCH + k * 32 + t4 * 4;
                    u32 pbh0 = *(const u32*)(smraw + B_PHI + bb);
                    u32 pbh1 = *(const u32*)(smraw + B_PHI + bb + 16);
                    u32 pbl0 = *(const u32*)(smraw + B_PLO + bb);
                    u32 pbl1 = *(const u32*)(smraw + B_PLO + bb + 16);
                    u32 tbh0 = *(const u32*)(smraw + B_THI + bb);
                    u32 tbh1 = *(const u32*)(smraw + B_THI + bb + 16);
                    #pragma unroll
                    for (int mm = 0; mm < 2; ++mm) {
                        int fi = (mm * 4 + k) * 4;
                        MMA16816(dP[mm][0],dP[mm][1],dP[mm][2],dP[mm][3],
                                 aSPH[fi],aSPH[fi+1],aSPH[fi+2],aSPH[fi+3], pbh0,pbh1);
                        MMA16816(dP[mm][0],dP[mm][1],dP[mm][2],dP[mm][3],
                                 aSPH[fi],aSPH[fi+1],aSPH[fi+2],aSPH[fi+3], pbl0,pbl1);
                        MMA16816(dT[mm][0],dT[mm][1],dT[mm][2],dT[mm][3],
                                 aSGH[fi],aSGH[fi+1],aSGH[fi+2],aSGH[fi+3], tbh0,tbh1);
                    }
                }
                // epilogue for this n-tile: cols c0 = n*8+2t4, c0+1 (MUFU acts)
                int c0 = n * 8 + 2 * t4;
                float4 cw0 = colw[c0];
                float4 cw1 = colw[c0 + 1];
                float hb0 = fmaf(cw0.x, te, cw0.y);
                float hb1 = fmaf(cw1.x, te, cw1.y);
                #pragma unroll
                for (int mm = 0; mm < 2; ++mm) {
                    float spa, spb, sga, sgb;
                    act1m(dP[mm][0] + hb0, spa, sga);
                    act1m(dP[mm][1] + hb1, spb, sgb);
                    zr0[2*mm] = fmaf(cw0.z, spa, zr0[2*mm]);
                    zr0[2*mm] = fmaf(cw1.z, spb, zr0[2*mm]);
                    zr1[2*mm] = fmaf(cw0.w, spa, zr1[2*mm]);
                    zr1[2*mm] = fmaf(cw1.w, spb, zr1[2*mm]);
                    trr[2*mm] = fmaf(sga, dT[mm][0], trr[2*mm]);
                    trr[2*mm] = fmaf(sgb, dT[mm][1], trr[2*mm]);
                    act1m(dP[mm][2] + hb0, spa, sga);
                    act1m(dP[mm][3] + hb1, spb, sgb);
                    zr0[2*mm+1] = fmaf(cw0.z, spa, zr0[2*mm+1]);
                    zr0[2*mm+1] = fmaf(cw1.z, spb, zr0[2*mm+1]);
                    zr1[2*mm+1] = fmaf(cw0.w, spa, zr1[2*mm+1]);
                    zr1[2*mm+1] = fmaf(cw1.w, spb, zr1[2*mm+1]);
                    trr[2*mm+1] = fmaf(sga, dT[mm][2], trr[2*mm+1]);
                    trr[2*mm+1] = fmaf(sgb, dT[mm][3], trr[2*mm+1]);
                }
            }

            // ---- quad reduction via per-warp smem scratch (aliases consumed A rows)
            unsigned char* red = smraw + A_SPHI + warp * 32 * PITCH;
            #pragma unroll
            for (int r4 = 0; r4 < 4; ++r4) {
                int row = r4 * 8 + g;
                float* pr = (float*)(red + row * 48 + t4 * 12);
                pr[0] = zr0[r4]; pr[1] = zr1[r4]; pr[2] = trr[r4];
            }
            __syncwarp();
            float s0 = 0.f, s1 = 0.f, stv = 0.f;
            #pragma unroll
            for (int q = 0; q < 4; ++q) {
                const float* pr = (const float*)(red + lane * 48 + q * 12);
                s0 += pr[0]; s1 += pr[1]; stv += pr[2];
            }
            __syncwarp();

            float k0 = s0 + fmaf(scal.x, te, scal.z);
            float k1 = s1 + fmaf(scal.y, te, scal.w);
            float klv = -stv;

            acc0 = fmaf(ws, k0, acc0);
            acc1 = fmaf(ws, k1, acc1);
            accl = fmaf(ws, klv, accl);
            pk0v = k0; pk1v = k1;
        }
        const float c6 = dt / 6.0f;
        z0 = fmaf(c6, acc0, z0);
        z1 = fmaf(c6, acc1, z1);
        lp = fmaf(c6, accl, lp);
    }

    if (gid < B) {
        reinterpret_cast<float2*>(out)[gid] = make_float2(z0, z1);  // zf: (B,2)
        out[2 * B + gid] = lp;                                      // delta_logpz: (B,1)
    }
}

extern "C" void kernel_launch(void* const* d_in, const int* in_sizes, int n_in,
                              void* d_out, int out_size) {
    const float2* z  = (const float2*)d_in[0];
    const float* dlp = (const float*)d_in[1];
    const float* W1  = (const float*)d_in[2];
    const float* b1  = (const float*)d_in[3];
    const float* W2  = (const float*)d_in[4];
    const float* b2  = (const float*)d_in[5];
    const float* W3  = (const float*)d_in[6];
    const float* b3  = (const float*)d_in[7];
    float* out = (float*)d_out;
    int B = in_sizes[0] / 2;

    // Host-side, enqueues nothing -> graph-capture safe. Idempotent.
    cudaFuncSetAttribute(ffjord_mma_kernel, cudaFuncAttributeMaxDynamicSharedMemorySize,
                         SMEM_BYTES);

    int blocks = (B + 127) / 128;
    ffjord_mma_kernel<<<blocks, 128, SMEM_BYTES>>>(z, dlp, W1, b1, W2, b2, W3, b3, out, B);
}